// round 8
// baseline (speedup 1.0000x reference)
#include <cuda_runtime.h>
#include <math.h>

// FLIF fractional LIF — round 6.
// Rotating age-ownership + f32x2 packing (2 neurons/thread), with the mem
// broadcast PIPELINED OFF the critical chain:
//   mem_d = bcast_{d-3} + wr2*delta_{d-2} + wr1*delta_{d-1}
// bcast_{d-3} = lane0's slot for dest d after step (d-3)'s scatter (ages>=3).
// Each step shfls the dest n+3 slot (3 steps of slack); the last two memory
// terms are finished locally by every lane (all lanes compute delta anyway).

#define T_STEPS 384
typedef unsigned long long u64;

__device__ __forceinline__ u64 pack2(float x, float y) {
    u64 r; asm("mov.b64 %0, {%1, %2};" : "=l"(r) : "f"(x), "f"(y)); return r;
}
__device__ __forceinline__ void unpack2(u64 a, float& x, float& y) {
    asm("mov.b64 {%0, %1}, %2;" : "=f"(x), "=f"(y) : "l"(a));
}
__device__ __forceinline__ u64 fma2(u64 a, u64 b, u64 c) {
    u64 d; asm("fma.rn.f32x2 %0, %1, %2, %3;" : "=l"(d) : "l"(a), "l"(b), "l"(c)); return d;
}
__device__ __forceinline__ u64 add2(u64 a, u64 b) {
    u64 d; asm("add.rn.f32x2 %0, %1, %2;" : "=l"(d) : "l"(a), "l"(b)); return d;
}

struct St {
    u64 M[12];      // negated-memory accumulators (cyclic by age)
    u64 wrn[12];    // wrn[m] = (-wr[12*lane+m+1]) packed in both halves
    u64 w1n, w2n;   // (-wr[1], -wr[1]), (-wr[2], -wr[2])  (uniform)
    u64 cA, cG, cC; // (-1.75,-1.75), (-0.025,-0.025), (COEF,COEF)
    u64 memF;       // fully-resolved negated mem for the CURRENT step
    u64 memP;       // partial for next step (missing only wr1*delta_n)
    u64 bc;         // look-ahead broadcast (dest n+2 partial, ages>=3)
    u64 V2;         // packed V
    float Vlo, Vhi;
    bool is0, is31;
    int lnext;
};

// One uniform step for n >= 2.  RR = n % 12 (compile-time).
template<int RR>
__device__ __forceinline__ void step(St& s, const float2* __restrict__ inw,
                                     float2* __restrict__ trcw, int idx)
{
    // handoff (needed only as new tail, 12 steps of slack)
    u64 tmp = __shfl_sync(0xffffffffu, s.M[RR], s.lnext);

    float2 In = inw[idx];
    u64 a2  = add2(pack2(In.x, In.y), s.cA);   // In - 1.75          (off-chain)
    u64 t2  = fma2(s.V2, s.cG, a2);            // -0.025*V + In - 1.75
    u64 u2  = fma2(t2, s.cC, s.V2);            // COEF*(...) + V
    u64 vp2 = add2(u2, s.memF);                // minus memory (memF negated)

    float vpl, vph; unpack2(vp2, vpl, vph);
    float vnl = vpl - ((s.Vlo > -50.0f) ? 20.0f : 0.0f);  // spike uses PREV V
    float vnh = vph - ((s.Vhi > -50.0f) ? 20.0f : 0.0f);
    u64 d2 = pack2(vnl - s.Vlo, vnh - s.Vhi);             // delta_n

    // memory pipeline (local, keeps shfl off the chain)
    s.memF = fma2(s.w1n, d2, s.memP);   // resolved mem for step n+1
    s.memP = fma2(s.w2n, d2, s.bc);     // partial for step n+2

    // cyclic tail refill + scatter
    s.M[RR] = s.is31 ? 0ull : tmp;
#pragma unroll
    for (int j = 0; j < 12; ++j)
        s.M[j] = fma2(s.wrn[(j + 11 - RR) % 12], d2, s.M[j]);

    // look-ahead broadcast: dest n+3 slot (physical (RR+3)%12), post-scatter
    s.bc = __shfl_sync(0xffffffffu, s.M[(RR + 3) % 12], 0);

    if (s.is0) trcw[idx] = make_float2(vnl, vnh);
    s.Vlo = vnl; s.Vhi = vnh; s.V2 = pack2(vnl, vnh);
}

__global__ __launch_bounds__(32) void flif_kernel(
    const float* __restrict__ I,    // [S, T]
    const float* __restrict__ Wt,   // weights, length Wlen
    float* __restrict__ out,        // [2, S, T]: spikes then trace
    int S, int Wlen, float COEF)
{
    __shared__ float2 in_sh[T_STEPS];
    __shared__ float2 trc_sh[T_STEPS];

    const int lane = threadIdx.x & 31;
    const int pair = blockIdx.x;
    const int sA = pair * 2, sB = sA + 1;

    const float* rowA = I + (size_t)sA * T_STEPS;
    const float* rowB = I + (size_t)sB * T_STEPS;
    for (int t = lane; t < T_STEPS; t += 32)
        in_sh[t] = make_float2(rowA[t], rowB[t]);
    __syncwarp();

    St s;
    s.is0 = (lane == 0);
    s.is31 = (lane == 31);
    s.lnext = (lane + 1) & 31;
    s.cA = pack2(-1.75f, -1.75f);
    s.cG = pack2(-0.025f, -0.025f);
    s.cC = pack2(COEF, COEF);
    {
        float w1 = -Wt[Wlen - 1];
        float w2 = -Wt[Wlen - 2];
        s.w1n = pack2(w1, w1);
        s.w2n = pack2(w2, w2);
    }
#pragma unroll
    for (int m = 0; m < 12; ++m) {
        float v = -Wt[Wlen - (12 * lane + m + 1)];   // -wr[12*lane+m+1]
        s.wrn[m] = pack2(v, v);
    }
#pragma unroll
    for (int j = 0; j < 12; ++j) s.M[j] = 0ull;

    // ---- step 0 (exact): V_prev=0 -> spike, Vpre=-70, Vnew=-90; delta_0 NOT scattered
    s.Vlo = -90.0f; s.Vhi = -90.0f; s.V2 = pack2(-90.0f, -90.0f);
    if (s.is0) trc_sh[0] = make_float2(-90.0f, -90.0f);

    // ---- step 1 (exact): V1 = V + 0.005*(-V + I*40); spike=0; mem=0
    {
        float2 In = in_sh[1];
        float vnl = s.Vlo + 0.005f * (-s.Vlo + In.x * 40.0f);
        float vnh = s.Vhi + 0.005f * (-s.Vhi + In.y * 40.0f);
        u64 d1 = pack2(vnl - s.Vlo, vnh - s.Vhi);
#pragma unroll
        for (int j = 0; j < 12; ++j)                 // scatter delta_1 (r = 1)
            s.M[j] = fma2(s.wrn[(j + 10) % 12], d1, s.M[j]);
        s.Vlo = vnl; s.Vhi = vnh; s.V2 = pack2(vnl, vnh);
        if (s.is0) trc_sh[1] = make_float2(vnl, vnh);

        // pipeline init for uniform start at n=2:
        //   memF (mem_2)      = -wr1*d1
        //   memP (dest 3)     = -wr2*d1            (bcast_0 = 0)
        //   bc   (bcast_1, dest 4, ages>=3) = -wr3*d1
        float w3 = -Wt[Wlen - 3];
        s.memF = fma2(s.w1n, d1, 0ull);
        s.memP = fma2(s.w2n, d1, 0ull);
        s.bc   = fma2(pack2(w3, w3), d1, 0ull);
    }

    // ---- main loop: n = 2 .. 373, 31 iterations of 12 steps
#define BODY12(NB)                              \
    step<2>(s, in_sh, trc_sh, (NB) + 0);        \
    step<3>(s, in_sh, trc_sh, (NB) + 1);        \
    step<4>(s, in_sh, trc_sh, (NB) + 2);        \
    step<5>(s, in_sh, trc_sh, (NB) + 3);        \
    step<6>(s, in_sh, trc_sh, (NB) + 4);        \
    step<7>(s, in_sh, trc_sh, (NB) + 5);        \
    step<8>(s, in_sh, trc_sh, (NB) + 6);        \
    step<9>(s, in_sh, trc_sh, (NB) + 7);        \
    step<10>(s, in_sh, trc_sh, (NB) + 8);       \
    step<11>(s, in_sh, trc_sh, (NB) + 9);       \
    step<0>(s, in_sh, trc_sh, (NB) + 10);       \
    step<1>(s, in_sh, trc_sh, (NB) + 11);

    for (int nb = 2; nb <= T_STEPS - 22; nb += 12) {   // nb = 2,14,...,362
        BODY12(nb)
    }
    // ---- epilogue: n = 374..383
    step<2>(s, in_sh, trc_sh, 374);
    step<3>(s, in_sh, trc_sh, 375);
    step<4>(s, in_sh, trc_sh, 376);
    step<5>(s, in_sh, trc_sh, 377);
    step<6>(s, in_sh, trc_sh, 378);
    step<7>(s, in_sh, trc_sh, 379);
    step<8>(s, in_sh, trc_sh, 380);
    step<9>(s, in_sh, trc_sh, 381);
    step<10>(s, in_sh, trc_sh, 382);
    step<11>(s, in_sh, trc_sh, 383);
#undef BODY12

    __syncwarp();

    // ---- dump: trace directly; spikes derived from trace[t-1]
    const size_t baseA = (size_t)sA * T_STEPS;
    const size_t baseB = (size_t)sB * T_STEPS;
    const size_t off   = (size_t)S * T_STEPS;
    for (int t = lane; t < T_STEPS; t += 32) {
        float2 v = trc_sh[t];
        out[off + baseA + t] = v.x;
        out[off + baseB + t] = v.y;
        float sl, sh;
        if (t == 0) { sl = 1.0f; sh = 1.0f; }   // V_prev = 0 > -50
        else {
            float2 vp = trc_sh[t - 1];
            sl = (vp.x > -50.0f) ? 1.0f : 0.0f;
            sh = (vp.y > -50.0f) ? 1.0f : 0.0f;
        }
        out[baseA + t] = sl;
        out[baseB + t] = sh;
    }
}

extern "C" void kernel_launch(void* const* d_in, const int* in_sizes, int n_in,
                              void* d_out, int out_size)
{
    const float* I  = (const float*)d_in[0];
    const float* Wt = (const float*)d_in[1];
    float* out = (float*)d_out;

    const int S    = in_sizes[0] / T_STEPS;
    const int Wlen = in_sizes[1];

    const float coef = (float)(pow(0.1, 0.15) * tgamma(2.0 - 0.15) / 0.5);

    const int pairs = S / 2;                 // S = 2048 -> 1024 warp-blocks
    flif_kernel<<<pairs, 32>>>(I, Wt, out, S, Wlen, coef);
}

// round 9
// speedup vs baseline: 1.1493x; 1.1493x over previous
#include <cuda_runtime.h>
#include <math.h>

// FLIF fractional LIF — round 9.  (R6 look-ahead reverted: it was a regression.)
// R5 structure + TWO independent chains per warp (4 neurons/thread-warp, two
// f32x2 pairs). With only ~1.7 warps/SMSP the single-chain serial section
// pinned issue at 44%; chain B's independent 12-FMA scatter burst fills the
// slots while chain A is serial. wrn weight registers are SHARED between the
// chains (same lane->age ownership), so state cost is only +M[12]+V.

#define T_STEPS 384
typedef unsigned long long u64;

__device__ __forceinline__ u64 pack2(float x, float y) {
    u64 r; asm("mov.b64 %0, {%1, %2};" : "=l"(r) : "f"(x), "f"(y)); return r;
}
__device__ __forceinline__ void unpack2(u64 a, float& x, float& y) {
    asm("mov.b64 {%0, %1}, %2;" : "=f"(x), "=f"(y) : "l"(a));
}
__device__ __forceinline__ u64 fma2(u64 a, u64 b, u64 c) {
    u64 d; asm("fma.rn.f32x2 %0, %1, %2, %3;" : "=l"(d) : "l"(a), "l"(b), "l"(c)); return d;
}
__device__ __forceinline__ u64 add2(u64 a, u64 b) {
    u64 d; asm("add.rn.f32x2 %0, %1, %2;" : "=l"(d) : "l"(a), "l"(b)); return d;
}

struct Chain {
    u64 M[12];      // negated-memory accumulators (cyclic by age)
    u64 V2;
    float Vlo, Vhi;
};

struct Shared {
    u64 wrn[12];    // wrn[m] = (-wr[12*lane+m+1]) both halves (SHARED by chains)
    u64 cA, cG, cC; // (-1.75), (-0.025), (COEF) packed
    bool is0, is31;
    int lnext;
};

// One uniform step (n >= 2) for one chain.  RR = n % 12 (compile-time).
template<int RR>
__device__ __forceinline__ void step1(Chain& c, const Shared& s,
                                      float inx, float iny,
                                      float& vnl_out, float& vnh_out)
{
    u64 mem2 = __shfl_sync(0xffffffffu, c.M[RR], 0);        // dest n (complete)
    u64 tmp  = __shfl_sync(0xffffffffu, c.M[RR], s.lnext);  // handoff lane+1 -> lane

    u64 a2  = add2(pack2(inx, iny), s.cA);   // In - 1.75
    u64 t2  = fma2(c.V2, s.cG, a2);          // -0.025*V + In - 1.75
    u64 u2  = fma2(t2, s.cC, c.V2);          // COEF*(...) + V
    u64 vp2 = add2(u2, mem2);                // minus memory (mem negated)

    float vpl, vph; unpack2(vp2, vpl, vph);
    float vnl = vpl - ((c.Vlo > -50.0f) ? 20.0f : 0.0f);  // spike uses PREV V
    float vnh = vph - ((c.Vhi > -50.0f) ? 20.0f : 0.0f);
    u64 d2 = pack2(vnl - c.Vlo, vnh - c.Vhi);             // delta_n

    c.M[RR] = s.is31 ? 0ull : tmp;           // consumed slot becomes new tail
#pragma unroll
    for (int j = 0; j < 12; ++j)
        c.M[j] = fma2(s.wrn[(j + 11 - RR) % 12], d2, c.M[j]);

    c.Vlo = vnl; c.Vhi = vnh; c.V2 = pack2(vnl, vnh);
    vnl_out = vnl; vnh_out = vnh;
}

// Both chains per step; single LDS.128 in, single predicated STS.128 out.
template<int RR>
__device__ __forceinline__ void step2(Chain& A, Chain& B, const Shared& s,
                                      const float4* __restrict__ inw,
                                      float4* __restrict__ trcw, int idx)
{
    float4 In = inw[idx];
    float al, ah, bl, bh;
    step1<RR>(A, s, In.x, In.y, al, ah);
    step1<RR>(B, s, In.z, In.w, bl, bh);
    if (s.is0) trcw[idx] = make_float4(al, ah, bl, bh);
}

__global__ __launch_bounds__(32) void flif_kernel(
    const float* __restrict__ I,    // [S, T]
    const float* __restrict__ Wt,   // weights, length Wlen
    float* __restrict__ out,        // [2, S, T]: spikes then trace
    int S, int Wlen, float COEF)
{
    __shared__ float4 in_sh[T_STEPS];
    __shared__ float4 trc_sh[T_STEPS];

    const int lane = threadIdx.x & 31;
    const int s0 = blockIdx.x * 4;          // neurons s0 .. s0+3

    const float* r0 = I + (size_t)(s0 + 0) * T_STEPS;
    const float* r1 = I + (size_t)(s0 + 1) * T_STEPS;
    const float* r2 = I + (size_t)(s0 + 2) * T_STEPS;
    const float* r3 = I + (size_t)(s0 + 3) * T_STEPS;
    for (int t = lane; t < T_STEPS; t += 32)
        in_sh[t] = make_float4(r0[t], r1[t], r2[t], r3[t]);
    __syncwarp();

    Shared s;
    s.is0 = (lane == 0);
    s.is31 = (lane == 31);
    s.lnext = (lane + 1) & 31;
    s.cA = pack2(-1.75f, -1.75f);
    s.cG = pack2(-0.025f, -0.025f);
    s.cC = pack2(COEF, COEF);
#pragma unroll
    for (int m = 0; m < 12; ++m) {
        float v = -Wt[Wlen - (12 * lane + m + 1)];   // -wr[12*lane+m+1]
        s.wrn[m] = pack2(v, v);
    }

    Chain A, B;
#pragma unroll
    for (int j = 0; j < 12; ++j) { A.M[j] = 0ull; B.M[j] = 0ull; }

    // ---- step 0 (exact): V_prev=0 -> spike, Vpre=-70, Vnew=-90; delta_0 NOT scattered
    A.Vlo = A.Vhi = B.Vlo = B.Vhi = -90.0f;
    A.V2 = B.V2 = pack2(-90.0f, -90.0f);
    if (s.is0) trc_sh[0] = make_float4(-90.0f, -90.0f, -90.0f, -90.0f);

    // ---- step 1 (exact): V1 = V + 0.005*(-V + I*40); spike=0; mem=0
    {
        float4 In = in_sh[1];
        float a0 = A.Vlo + 0.005f * (-A.Vlo + In.x * 40.0f);
        float a1 = A.Vhi + 0.005f * (-A.Vhi + In.y * 40.0f);
        float b0 = B.Vlo + 0.005f * (-B.Vlo + In.z * 40.0f);
        float b1 = B.Vhi + 0.005f * (-B.Vhi + In.w * 40.0f);
        u64 dA = pack2(a0 - A.Vlo, a1 - A.Vhi);
        u64 dB = pack2(b0 - B.Vlo, b1 - B.Vhi);
#pragma unroll
        for (int j = 0; j < 12; ++j) {               // scatter delta_1 (r = 1)
            A.M[j] = fma2(s.wrn[(j + 10) % 12], dA, A.M[j]);
            B.M[j] = fma2(s.wrn[(j + 10) % 12], dB, B.M[j]);
        }
        A.Vlo = a0; A.Vhi = a1; A.V2 = pack2(a0, a1);
        B.Vlo = b0; B.Vhi = b1; B.V2 = pack2(b0, b1);
        if (s.is0) trc_sh[1] = make_float4(a0, a1, b0, b1);
    }

    // ---- main loop: n = 2 .. 373, 31 iterations of 12 steps
#define BODY12(NB)                              \
    step2<2>(A, B, s, in_sh, trc_sh, (NB) + 0); \
    step2<3>(A, B, s, in_sh, trc_sh, (NB) + 1); \
    step2<4>(A, B, s, in_sh, trc_sh, (NB) + 2); \
    step2<5>(A, B, s, in_sh, trc_sh, (NB) + 3); \
    step2<6>(A, B, s, in_sh, trc_sh, (NB) + 4); \
    step2<7>(A, B, s, in_sh, trc_sh, (NB) + 5); \
    step2<8>(A, B, s, in_sh, trc_sh, (NB) + 6); \
    step2<9>(A, B, s, in_sh, trc_sh, (NB) + 7); \
    step2<10>(A, B, s, in_sh, trc_sh, (NB) + 8); \
    step2<11>(A, B, s, in_sh, trc_sh, (NB) + 9); \
    step2<0>(A, B, s, in_sh, trc_sh, (NB) + 10); \
    step2<1>(A, B, s, in_sh, trc_sh, (NB) + 11);

    for (int nb = 2; nb <= T_STEPS - 22; nb += 12) {   // nb = 2,14,...,362
        BODY12(nb)
    }
    // ---- epilogue: n = 374..383
    step2<2>(A, B, s, in_sh, trc_sh, 374);
    step2<3>(A, B, s, in_sh, trc_sh, 375);
    step2<4>(A, B, s, in_sh, trc_sh, 376);
    step2<5>(A, B, s, in_sh, trc_sh, 377);
    step2<6>(A, B, s, in_sh, trc_sh, 378);
    step2<7>(A, B, s, in_sh, trc_sh, 379);
    step2<8>(A, B, s, in_sh, trc_sh, 380);
    step2<9>(A, B, s, in_sh, trc_sh, 381);
    step2<10>(A, B, s, in_sh, trc_sh, 382);
    step2<11>(A, B, s, in_sh, trc_sh, 383);
#undef BODY12

    __syncwarp();

    // ---- dump: trace directly; spikes derived from trace[t-1] (spike_t = V_{t-1} > -50)
    const size_t b0 = (size_t)(s0 + 0) * T_STEPS;
    const size_t b1 = (size_t)(s0 + 1) * T_STEPS;
    const size_t b2 = (size_t)(s0 + 2) * T_STEPS;
    const size_t b3 = (size_t)(s0 + 3) * T_STEPS;
    const size_t off = (size_t)S * T_STEPS;
    for (int t = lane; t < T_STEPS; t += 32) {
        float4 v = trc_sh[t];
        out[off + b0 + t] = v.x;
        out[off + b1 + t] = v.y;
        out[off + b2 + t] = v.z;
        out[off + b3 + t] = v.w;
        float s0f, s1f, s2f, s3f;
        if (t == 0) { s0f = s1f = s2f = s3f = 1.0f; }   // V_prev = 0 > -50
        else {
            float4 vp = trc_sh[t - 1];
            s0f = (vp.x > -50.0f) ? 1.0f : 0.0f;
            s1f = (vp.y > -50.0f) ? 1.0f : 0.0f;
            s2f = (vp.z > -50.0f) ? 1.0f : 0.0f;
            s3f = (vp.w > -50.0f) ? 1.0f : 0.0f;
        }
        out[b0 + t] = s0f;
        out[b1 + t] = s1f;
        out[b2 + t] = s2f;
        out[b3 + t] = s3f;
    }
}

extern "C" void kernel_launch(void* const* d_in, const int* in_sizes, int n_in,
                              void* d_out, int out_size)
{
    const float* I  = (const float*)d_in[0];
    const float* Wt = (const float*)d_in[1];
    float* out = (float*)d_out;

    const int S    = in_sizes[0] / T_STEPS;
    const int Wlen = in_sizes[1];

    const float coef = (float)(pow(0.1, 0.15) * tgamma(2.0 - 0.15) / 0.5);

    const int quads = S / 4;                 // S = 2048 -> 512 warp-blocks
    flif_kernel<<<quads, 32>>>(I, Wt, out, S, Wlen, coef);
}